// round 1
// baseline (speedup 1.0000x reference)
#include <cuda_runtime.h>

// ---------------------------------------------------------------------------
// SFMCNN: 3 towers of (RBF-conv -> triangle -> crelu -> alpha-pool) x2 + conv
// then flatten + FC.  All fp32.  Scratch lives in __device__ globals.
// ---------------------------------------------------------------------------

#define NB   128   // batch
#define NT   3     // towers
#define NBT  (NB*NT)

// scratch buffers
__device__ float g_a1[NBT * 64 * 24 * 24];    // pooled layer1 output
__device__ float g_a2[NBT * 128 * 12 * 12];   // pooled layer2 output
__device__ float g_a3[NB * 110592];           // layer3 output, FC-ready layout
__device__ float g_xsq2[NBT * 24 * 24];
__device__ float g_xsq3[NBT * 12 * 12];
__device__ float g_wsq2[NT * 128];
__device__ float g_wsq3[NT * 256];

#define FC_SLABS 216
#define FC_SLAB_K 512                          // 216*512 = 110592
__device__ float g_part[FC_SLABS * NB * 100];

// ---------------------------------------------------------------------------
// prep: ||w||^2 for layers 2 and 3
// ---------------------------------------------------------------------------
__global__ void k_wsq(const float* __restrict__ W2, const float* __restrict__ W3) {
    int tid = blockIdx.x * blockDim.x + threadIdx.x;
    if (tid < NT * 128) {
        const float* p = W2 + tid * 576;
        float s = 0.f;
        for (int k = 0; k < 576; ++k) s += p[k] * p[k];
        g_wsq2[tid] = s;
    } else if (tid < NT * 128 + NT * 256) {
        int o = tid - NT * 128;
        const float* p = W3 + o * 1152;
        float s = 0.f;
        for (int k = 0; k < 1152; ++k) s += p[k] * p[k];
        g_wsq3[o] = s;
    }
}

// ---------------------------------------------------------------------------
// layer 1: RBF conv 5x5 (C=1 -> 64) on 48x48, pad 2 + triangle + crelu + pool
// one block per (b,t). 256 threads: 4 threads per output channel.
// ---------------------------------------------------------------------------
__global__ void __launch_bounds__(256) k_layer1(
    const float* __restrict__ x, const float* __restrict__ W1,
    const float* __restrict__ tri_w, const float* __restrict__ crelu_b,
    const float* __restrict__ sfm_alpha)
{
    __shared__ __align__(16) float xpad[52 * 52];
    __shared__ float xsqs[48 * 48];
    __shared__ float w1s[64 * 25];
    __shared__ float wsq1s[64];

    const int bt = blockIdx.x;
    const int t = bt % NT;
    const int tid = threadIdx.x;

    for (int idx = tid; idx < 52 * 52; idx += 256) xpad[idx] = 0.f;
    __syncthreads();
    for (int idx = tid; idx < 48 * 48; idx += 256) {
        int y = idx / 48, xx = idx % 48;
        xpad[(y + 2) * 52 + xx + 2] = x[bt * 2304 + idx];
    }
    for (int idx = tid; idx < 64 * 25; idx += 256) w1s[idx] = W1[t * 1600 + idx];
    __syncthreads();

    if (tid < 64) {
        float s = 0.f;
        #pragma unroll
        for (int k = 0; k < 25; ++k) { float w = w1s[tid * 25 + k]; s += w * w; }
        wsq1s[tid] = s;
    }
    // per-pixel window sum of squares (shared over all 64 channels)
    for (int idx = tid; idx < 48 * 48; idx += 256) {
        int y = idx / 48, xx = idx % 48;
        float s = 0.f;
        #pragma unroll
        for (int ky = 0; ky < 5; ++ky)
            #pragma unroll
            for (int kx = 0; kx < 5; ++kx) {
                float v = xpad[(y + ky) * 52 + xx + kx];
                s += v * v;
            }
        xsqs[idx] = s;
    }
    __syncthreads();

    const int o = tid >> 2, sub = tid & 3;
    float wr[25];
    #pragma unroll
    for (int k = 0; k < 25; ++k) wr[k] = w1s[o * 25 + k];
    const float wq = wsq1s[o];
    const float tw = tri_w[t * 3 + 0], inv_tw = 1.f / tw;
    const float cb = crelu_b[t * 3 + 0];
    const float al = sfm_alpha[t * 2 + 0];
    const float c00 = al * al * al * 0.25f, c01 = al * al * 0.25f;
    const float c10 = al * 0.25f, c11 = 0.25f;

    for (int it = 0; it < 144; ++it) {
        int p = it * 4 + sub;
        int i = p / 24, j = p % 24;
        float pt[6][6];
        #pragma unroll
        for (int r = 0; r < 6; ++r) {
            const float* row = &xpad[(2 * i + r) * 52 + 2 * j];
            #pragma unroll
            for (int s2 = 0; s2 < 3; ++s2) {
                float2 u = *(const float2*)(row + 2 * s2);
                pt[r][2 * s2] = u.x; pt[r][2 * s2 + 1] = u.y;
            }
        }
        float vv[2][2];
        #pragma unroll
        for (int a = 0; a < 2; ++a)
            #pragma unroll
            for (int b2 = 0; b2 < 2; ++b2) {
                float cr = 0.f;
                #pragma unroll
                for (int ky = 0; ky < 5; ++ky)
                    #pragma unroll
                    for (int kx = 0; kx < 5; ++kx)
                        cr += wr[ky * 5 + kx] * pt[a + ky][b2 + kx];
                float d = xsqs[(2 * i + a) * 48 + 2 * j + b2] - 2.f * cr + wq;
                d = fmaxf(d, 0.f);
                float v = 1.f - fminf(d, tw) * inv_tw;
                vv[a][b2] = (v >= cb) ? v : 0.f;
            }
        g_a1[(bt * 64 + o) * 576 + p] =
            c00 * vv[0][0] + c01 * vv[0][1] + c10 * vv[1][0] + c11 * vv[1][1];
    }
}

// ---------------------------------------------------------------------------
// xsq maps for layers 2 / 3: window(3x3, zero-pad) of sum_c a^2
// ---------------------------------------------------------------------------
__global__ void k_xsq2() {
    __shared__ float s[576];
    const int bt = blockIdx.x, tid = threadIdx.x;
    for (int p = tid; p < 576; p += 256) {
        float acc = 0.f;
        for (int c = 0; c < 64; ++c) {
            float v = g_a1[(bt * 64 + c) * 576 + p];
            acc += v * v;
        }
        s[p] = acc;
    }
    __syncthreads();
    for (int p = tid; p < 576; p += 256) {
        int y = p / 24, xx = p % 24;
        float acc = 0.f;
        #pragma unroll
        for (int dy = -1; dy <= 1; ++dy)
            #pragma unroll
            for (int dx = -1; dx <= 1; ++dx) {
                int yy = y + dy, xc = xx + dx;
                if (yy >= 0 && yy < 24 && xc >= 0 && xc < 24) acc += s[yy * 24 + xc];
            }
        g_xsq2[bt * 576 + p] = acc;
    }
}

__global__ void k_xsq3() {
    __shared__ float s[144];
    const int bt = blockIdx.x, tid = threadIdx.x;
    if (tid < 144) {
        float acc = 0.f;
        for (int c = 0; c < 128; ++c) {
            float v = g_a2[(bt * 128 + c) * 144 + tid];
            acc += v * v;
        }
        s[tid] = acc;
    }
    __syncthreads();
    if (tid < 144) {
        int y = tid / 12, xx = tid % 12;
        float acc = 0.f;
        #pragma unroll
        for (int dy = -1; dy <= 1; ++dy)
            #pragma unroll
            for (int dx = -1; dx <= 1; ++dx) {
                int yy = y + dy, xc = xx + dx;
                if (yy >= 0 && yy < 12 && xc >= 0 && xc < 12) acc += s[yy * 12 + xc];
            }
        g_xsq3[bt * 144 + tid] = acc;
    }
}

// ---------------------------------------------------------------------------
// layer 2: RBF conv 3x3 (64 -> 128) on 24x24, pad 1 + tri/crelu + pool
// grid (NBT, 8): 16 out channels per block.  288 threads: thread = (oc8, pooled
// position); 8 channels x 2x2 conv quad per thread -> 32 accumulators.
// ---------------------------------------------------------------------------
__global__ void __launch_bounds__(288) k_layer2(
    const float* __restrict__ W2, const float* __restrict__ tri_w,
    const float* __restrict__ crelu_b, const float* __restrict__ sfm_alpha)
{
    __shared__ __align__(16) float inPad[8 * 26 * 26];
    __shared__ __align__(16) float w_s[16 * 8 * 12];   // taps padded 9 -> 12

    const int bt = blockIdx.x, t = bt % NT;
    const int oBase = blockIdx.y * 16;
    const int tid = threadIdx.x;
    const int oc8 = tid / 144, pp = tid % 144;
    const int i = pp / 12, j = pp % 12;

    for (int idx = tid; idx < 8 * 676; idx += 288) inPad[idx] = 0.f;

    float acc[8][4];
    #pragma unroll
    for (int ol = 0; ol < 8; ++ol)
        #pragma unroll
        for (int q = 0; q < 4; ++q) acc[ol][q] = 0.f;

    for (int cc = 0; cc < 8; ++cc) {
        __syncthreads();
        for (int idx = tid; idx < 8 * 576; idx += 288) {
            int c = idx / 576, p = idx % 576, y = p / 24, xx = p % 24;
            inPad[c * 676 + (y + 1) * 26 + xx + 1] =
                g_a1[(bt * 64 + cc * 8 + c) * 576 + p];
        }
        for (int idx = tid; idx < 16 * 72; idx += 288) {
            int ol = idx / 72, r = idx % 72, c = r / 9, tap = r % 9;
            w_s[(ol * 8 + c) * 12 + tap] =
                W2[(t * 128 + oBase + ol) * 576 + (cc * 8 + c) * 9 + tap];
        }
        __syncthreads();

        #pragma unroll
        for (int c = 0; c < 8; ++c) {
            float pt[4][4];
            #pragma unroll
            for (int r = 0; r < 4; ++r) {
                const float* row = &inPad[c * 676 + (2 * i + r) * 26 + 2 * j];
                float2 u = *(const float2*)row;
                float2 v = *(const float2*)(row + 2);
                pt[r][0] = u.x; pt[r][1] = u.y; pt[r][2] = v.x; pt[r][3] = v.y;
            }
            #pragma unroll
            for (int ol = 0; ol < 8; ++ol) {
                const float* wp = &w_s[((oc8 * 8 + ol) * 8 + c) * 12];
                float4 w0 = *(const float4*)wp;
                float4 w1 = *(const float4*)(wp + 4);
                float w8 = wp[8];
                #pragma unroll
                for (int a = 0; a < 2; ++a)
                    #pragma unroll
                    for (int b2 = 0; b2 < 2; ++b2) {
                        float s = acc[ol][a * 2 + b2];
                        s += w0.x * pt[a][b2];
                        s += w0.y * pt[a][b2 + 1];
                        s += w0.z * pt[a][b2 + 2];
                        s += w0.w * pt[a + 1][b2];
                        s += w1.x * pt[a + 1][b2 + 1];
                        s += w1.y * pt[a + 1][b2 + 2];
                        s += w1.z * pt[a + 2][b2];
                        s += w1.w * pt[a + 2][b2 + 1];
                        s += w8  * pt[a + 2][b2 + 2];
                        acc[ol][a * 2 + b2] = s;
                    }
            }
        }
    }

    const float tw = tri_w[t * 3 + 1], inv_tw = 1.f / tw;
    const float cb = crelu_b[t * 3 + 1];
    const float al = sfm_alpha[t * 2 + 1];
    const float c00 = al * al * al * 0.25f, c01 = al * al * 0.25f;
    const float c10 = al * 0.25f, c11 = 0.25f;

    float xs[4];
    #pragma unroll
    for (int a = 0; a < 2; ++a)
        #pragma unroll
        for (int b2 = 0; b2 < 2; ++b2)
            xs[a * 2 + b2] = g_xsq2[bt * 576 + (2 * i + a) * 24 + 2 * j + b2];

    #pragma unroll
    for (int ol = 0; ol < 8; ++ol) {
        int og = oBase + oc8 * 8 + ol;
        float wq = g_wsq2[t * 128 + og];
        float vv[4];
        #pragma unroll
        for (int q = 0; q < 4; ++q) {
            float d = fmaxf(xs[q] - 2.f * acc[ol][q] + wq, 0.f);
            float v = 1.f - fminf(d, tw) * inv_tw;
            vv[q] = (v >= cb) ? v : 0.f;
        }
        g_a2[(bt * 128 + og) * 144 + i * 12 + j] =
            c00 * vv[0] + c01 * vv[1] + c10 * vv[2] + c11 * vv[3];
    }
}

// ---------------------------------------------------------------------------
// layer 3: RBF conv 3x3 (128 -> 256) on 12x12, pad 1 + tri/crelu (no pool)
// grid (NBT, 4): 64 out channels per block.  288 threads = 8 oc-groups x 36
// 2x2 quads.
// ---------------------------------------------------------------------------
__global__ void __launch_bounds__(288) k_layer3(
    const float* __restrict__ W3, const float* __restrict__ tri_w,
    const float* __restrict__ crelu_b)
{
    __shared__ __align__(16) float inPad[8 * 14 * 14];
    __shared__ __align__(16) float w_s[64 * 8 * 12];

    const int bt = blockIdx.x, t = bt % NT, b = bt / NT;
    const int oBase = blockIdx.y * 64;
    const int tid = threadIdx.x;
    const int oc8 = tid / 36, qq = tid % 36;
    const int i = qq / 6, j = qq % 6;

    for (int idx = tid; idx < 8 * 196; idx += 288) inPad[idx] = 0.f;

    float acc[8][4];
    #pragma unroll
    for (int ol = 0; ol < 8; ++ol)
        #pragma unroll
        for (int q = 0; q < 4; ++q) acc[ol][q] = 0.f;

    for (int cc = 0; cc < 16; ++cc) {
        __syncthreads();
        for (int idx = tid; idx < 8 * 144; idx += 288) {
            int c = idx / 144, p = idx % 144, y = p / 12, xx = p % 12;
            inPad[c * 196 + (y + 1) * 14 + xx + 1] =
                g_a2[(bt * 128 + cc * 8 + c) * 144 + p];
        }
        for (int idx = tid; idx < 64 * 72; idx += 288) {
            int ol = idx / 72, r = idx % 72, c = r / 9, tap = r % 9;
            w_s[(ol * 8 + c) * 12 + tap] =
                W3[(t * 256 + oBase + ol) * 1152 + (cc * 8 + c) * 9 + tap];
        }
        __syncthreads();

        #pragma unroll
        for (int c = 0; c < 8; ++c) {
            float pt[4][4];
            #pragma unroll
            for (int r = 0; r < 4; ++r) {
                const float* row = &inPad[c * 196 + (2 * i + r) * 14 + 2 * j];
                float2 u = *(const float2*)row;
                float2 v = *(const float2*)(row + 2);
                pt[r][0] = u.x; pt[r][1] = u.y; pt[r][2] = v.x; pt[r][3] = v.y;
            }
            #pragma unroll
            for (int ol = 0; ol < 8; ++ol) {
                const float* wp = &w_s[((oc8 * 8 + ol) * 8 + c) * 12];
                float4 w0 = *(const float4*)wp;
                float4 w1 = *(const float4*)(wp + 4);
                float w8 = wp[8];
                #pragma unroll
                for (int a = 0; a < 2; ++a)
                    #pragma unroll
                    for (int b2 = 0; b2 < 2; ++b2) {
                        float s = acc[ol][a * 2 + b2];
                        s += w0.x * pt[a][b2];
                        s += w0.y * pt[a][b2 + 1];
                        s += w0.z * pt[a][b2 + 2];
                        s += w0.w * pt[a + 1][b2];
                        s += w1.x * pt[a + 1][b2 + 1];
                        s += w1.y * pt[a + 1][b2 + 2];
                        s += w1.z * pt[a + 2][b2];
                        s += w1.w * pt[a + 2][b2 + 1];
                        s += w8  * pt[a + 2][b2 + 2];
                        acc[ol][a * 2 + b2] = s;
                    }
            }
        }
    }

    const float tw = tri_w[t * 3 + 2], inv_tw = 1.f / tw;
    const float cb = crelu_b[t * 3 + 2];

    #pragma unroll
    for (int ol = 0; ol < 8; ++ol) {
        int og = oBase + oc8 * 8 + ol;
        float wq = g_wsq3[t * 256 + og];
        #pragma unroll
        for (int a = 0; a < 2; ++a)
            #pragma unroll
            for (int b2 = 0; b2 < 2; ++b2) {
                int y = 2 * i + a, xx = 2 * j + b2;
                float d = fmaxf(g_xsq3[bt * 144 + y * 12 + xx]
                                - 2.f * acc[ol][a * 2 + b2] + wq, 0.f);
                float v = 1.f - fminf(d, tw) * inv_tw;
                v = (v >= cb) ? v : 0.f;
                g_a3[b * 110592 + t * 36864 + og * 144 + y * 12 + xx] = v;
            }
    }
}

// ---------------------------------------------------------------------------
// FC: out[b,n] = sum_k a3[b,k] * fcw[n,k] + fcb[n]
// split-K into 216 slabs of 512, deterministic two-stage reduction.
// ---------------------------------------------------------------------------
__global__ void __launch_bounds__(320) k_fc_partial(const float* __restrict__ fcw) {
    __shared__ __align__(16) float w_s[100 * 32];
    __shared__ __align__(16) float a_s[128 * 34];

    const int blk = blockIdx.x, tid = threadIdx.x;
    const int k0 = blk * FC_SLAB_K;
    const int ng = tid / 16, bq = tid % 16;   // ng in [0,20), bq in [0,16)
    const int n0 = ng * 5;

    float acc[5][8];
    #pragma unroll
    for (int qn = 0; qn < 5; ++qn)
        #pragma unroll
        for (int r = 0; r < 8; ++r) acc[qn][r] = 0.f;

    for (int ch = 0; ch < 16; ++ch) {
        int kb = k0 + ch * 32;
        __syncthreads();
        for (int idx = tid; idx < 100 * 32; idx += 320)
            w_s[idx] = fcw[(idx >> 5) * 110592 + kb + (idx & 31)];
        for (int idx = tid; idx < 128 * 32; idx += 320) {
            int bb = idx >> 5, kk = idx & 31;
            a_s[bb * 34 + kk] = g_a3[bb * 110592 + kb + kk];
        }
        __syncthreads();
        #pragma unroll 4
        for (int kk = 0; kk < 32; kk += 2) {
            float2 av[8];
            #pragma unroll
            for (int r = 0; r < 8; ++r)
                av[r] = *(const float2*)&a_s[(bq + 16 * r) * 34 + kk];
            #pragma unroll
            for (int qn = 0; qn < 5; ++qn) {
                float2 wv = *(const float2*)&w_s[(n0 + qn) * 32 + kk];
                #pragma unroll
                for (int r = 0; r < 8; ++r)
                    acc[qn][r] += wv.x * av[r].x + wv.y * av[r].y;
            }
        }
    }
    #pragma unroll
    for (int qn = 0; qn < 5; ++qn)
        #pragma unroll
        for (int r = 0; r < 8; ++r)
            g_part[blk * 12800 + (bq + 16 * r) * 100 + n0 + qn] = acc[qn][r];
}

__global__ void k_fc_reduce(const float* __restrict__ fcb, float* __restrict__ out) {
    int idx = blockIdx.x * blockDim.x + threadIdx.x;
    if (idx >= NB * 100) return;
    int n = idx % 100;
    float s = fcb[n];
    for (int sb = 0; sb < FC_SLABS; ++sb) s += g_part[sb * 12800 + idx];
    out[idx] = s;
}

// ---------------------------------------------------------------------------
extern "C" void kernel_launch(void* const* d_in, const int* in_sizes, int n_in,
                              void* d_out, int out_size) {
    const float* x         = (const float*)d_in[0];
    const float* W1        = (const float*)d_in[1];
    const float* W2        = (const float*)d_in[2];
    const float* W3        = (const float*)d_in[3];
    const float* tri_w     = (const float*)d_in[4];
    const float* crelu_b   = (const float*)d_in[5];
    const float* sfm_alpha = (const float*)d_in[6];
    const float* fcw       = (const float*)d_in[7];
    const float* fcb       = (const float*)d_in[8];
    float* out = (float*)d_out;

    k_wsq<<<5, 256>>>(W2, W3);
    k_layer1<<<NBT, 256>>>(x, W1, tri_w, crelu_b, sfm_alpha);
    k_xsq2<<<NBT, 256>>>();
    k_layer2<<<dim3(NBT, 8), 288>>>(W2, tri_w, crelu_b, sfm_alpha);
    k_xsq3<<<NBT, 256>>>();
    k_layer3<<<dim3(NBT, 4), 288>>>(W3, tri_w, crelu_b);
    k_fc_partial<<<FC_SLABS, 320>>>(fcw);
    k_fc_reduce<<<(NB * 100 + 255) / 256, 256>>>(fcb, out);
}